// round 16
// baseline (speedup 1.0000x reference)
#include <cuda_runtime.h>
#include <math.h>
#include <stdint.h>

#define N_TOK 4096
#define DIM 320
#define HEADS 8
#define DHEAD 40
#define CTX_DIM 768
#define M_CTX 77
#define FF_INNER 1280
#define SCALE 0.15811388300841898f
#define LOG2E 1.4426950408889634f
#define K2DIM 160
#define K2CTX 384
#define K2FF 640

typedef unsigned long long ull;

// ---------------- tf32 m16n8k8 mma (attention) ---------------------------------
__device__ __forceinline__ void mma_tf32(float* d, const uint32_t* a, const uint32_t* b) {
    asm volatile("mma.sync.aligned.m16n8k8.row.col.f32.tf32.tf32.f32 "
        "{%0,%1,%2,%3}, {%4,%5,%6,%7}, {%8,%9}, {%0,%1,%2,%3};"
        : "+f"(d[0]), "+f"(d[1]), "+f"(d[2]), "+f"(d[3])
        : "r"(a[0]), "r"(a[1]), "r"(a[2]), "r"(a[3]), "r"(b[0]), "r"(b[1]));
}

// ---------------- bf16 m16n8k16 mma (GEMMs) -------------------------------------
__device__ __forceinline__ void mma_bf16(float* d, const uint32_t* a, const uint32_t* b) {
    asm volatile("mma.sync.aligned.m16n8k16.row.col.f32.bf16.bf16.f32 "
        "{%0,%1,%2,%3}, {%4,%5,%6,%7}, {%8,%9}, {%0,%1,%2,%3};"
        : "+f"(d[0]), "+f"(d[1]), "+f"(d[2]), "+f"(d[3])
        : "r"(a[0]), "r"(a[1]), "r"(a[2]), "r"(a[3]), "r"(b[0]), "r"(b[1]));
}

// split a pair of fp32 (x0=even k, x1=odd k) into packed bf16x2 hi + residual lo.
__device__ __forceinline__ void split_pack(float x0, float x1, uint32_t& h, uint32_t& l) {
    uint32_t hp;
    asm("cvt.rn.satfinite.bf16x2.f32 %0, %1, %2;" : "=r"(hp) : "f"(x1), "f"(x0));
    float f0 = __uint_as_float(hp << 16);
    float f1 = __uint_as_float(hp & 0xffff0000u);
    float r0 = x0 - f0;
    float r1 = x1 - f1;
    asm("cvt.rn.satfinite.bf16x2.f32 %0, %1, %2;" : "=r"(l) : "f"(r1), "f"(r0));
    h = hp;
}

// ---------------- scratch (device globals; no allocation allowed) ------------
__device__ float g_q[N_TOK * DIM];
__device__ float g_k[N_TOK * DIM];
__device__ float g_v[N_TOK * DIM];
__device__ float g_kc[M_CTX * DIM];
__device__ float g_vc[M_CTX * DIM];
__device__ float g_bff1p[2 * FF_INNER];
// split (packed bf16x2 hi/lo) activations
__device__ uint32_t g_hh[N_TOK * K2DIM];
__device__ uint32_t g_hl[N_TOK * K2DIM];
__device__ uint32_t g_oh[N_TOK * K2DIM];
__device__ uint32_t g_ol[N_TOK * K2DIM];
__device__ uint32_t g_ggh[N_TOK * K2FF];
__device__ uint32_t g_ggl[N_TOK * K2FF];
__device__ uint32_t g_ctxh[M_CTX * K2CTX];
__device__ uint32_t g_ctxl[M_CTX * K2CTX];
// split weights
#define WQ1_OFF 0
#define WK1_OFF 51200
#define WV1_OFF 102400
#define WO1_OFF 153600
#define WQ2_OFF 204800
#define WO2_OFF 256000
#define WK2_OFF 307200
#define WV2_OFF 430080
#define WFF1_OFF 552960
#define WFF2_OFF 962560
#define W_TOTAL 1167360
__device__ uint32_t g_wh[W_TOTAL];
__device__ uint32_t g_wl[W_TOTAL];

// ---------------- weight split prep ([K/2][N] packed pairs, optional col perm) --
struct WJob { const float* src; uint32_t* dh; uint32_t* dl; int N; int words; int permute; };
struct WTable { WJob j[10]; };

__global__ __launch_bounds__(256) void split_w_kernel(WTable tab) {
    WJob jb = tab.j[blockIdx.z];
    int half = jb.N >> 1;
    for (int w = blockIdx.x * 256 + threadIdx.x; w < jb.words; w += gridDim.x * 256) {
        int jj = w / jb.N, n = w - jj * jb.N;
        float x0 = jb.src[(size_t)(2 * jj) * jb.N + n];
        float x1 = jb.src[(size_t)(2 * jj + 1) * jb.N + n];
        uint32_t h, l; split_pack(x0, x1, h, l);
        int n2 = jb.permute ? ((n < half) ? 2 * n : 2 * (n - half) + 1) : n;
        jb.dh[(size_t)jj * jb.N + n2] = h;
        jb.dl[(size_t)jj * jb.N + n2] = l;
    }
}

// ---------------- bias permute for fused GEGLU -----------------------------------
__global__ __launch_bounds__(256) void perm_bias_kernel(const float* __restrict__ src,
                                                        float* __restrict__ dst) {
    int n = blockIdx.x * 256 + threadIdx.x;
    if (n >= 2 * FF_INNER) return;
    int n2 = (n < FF_INNER) ? 2 * n : 2 * (n - FF_INNER) + 1;
    dst[n2] = src[n];
}

// ---------------- A-operand split prep ([M][K/2] packed pairs) ------------------
__global__ __launch_bounds__(256) void split_a_kernel(const float* __restrict__ src,
                                                      uint32_t* __restrict__ dh,
                                                      uint32_t* __restrict__ dl,
                                                      int K2, int words) {
    int w = blockIdx.x * 256 + threadIdx.x;
    if (w >= words) return;
    int row = w / K2, p = w - row * K2;
    float x0 = src[(size_t)row * 2 * K2 + 2 * p];
    float x1 = src[(size_t)row * 2 * K2 + 2 * p + 1];
    uint32_t h, l; split_pack(x0, x1, h, l);
    dh[w] = h; dl[w] = l;
}

// ---------------- LayerNorm (warp per row, writes split bf16 pairs) -------------
__global__ __launch_bounds__(256) void ln_kernel(const float* __restrict__ x,
                                                 const float* __restrict__ g,
                                                 const float* __restrict__ b,
                                                 uint32_t* __restrict__ Hh,
                                                 uint32_t* __restrict__ Hl) {
    int w = threadIdx.x >> 5, lane = threadIdx.x & 31;
    int row = blockIdx.x * 8 + w;
    const float* xr = x + (size_t)row * DIM;
    float s = 0.f, s2 = 0.f;
    #pragma unroll
    for (int i = 0; i < 10; i++) {
        float v = xr[lane + 32 * i];
        s += v; s2 += v * v;
    }
    #pragma unroll
    for (int off = 16; off; off >>= 1) {
        s  += __shfl_xor_sync(~0u, s, off);
        s2 += __shfl_xor_sync(~0u, s2, off);
    }
    float mu = s * (1.f / DIM);
    float var = s2 * (1.f / DIM) - mu * mu;
    float rstd = rsqrtf(var + 1e-5f);
    #pragma unroll
    for (int sdx = 0; sdx < 5; sdx++) {
        int p = lane + 32 * sdx;
        float x0 = (xr[2 * p]     - mu) * rstd * g[2 * p]     + b[2 * p];
        float x1 = (xr[2 * p + 1] - mu) * rstd * g[2 * p + 1] + b[2 * p + 1];
        uint32_t h, l; split_pack(x0, x1, h, l);
        Hh[(size_t)row * K2DIM + p] = h;
        Hl[(size_t)row * K2DIM + p] = l;
    }
}

// ---------------- bf16x3 tensor-core GEMM 64x64, pre-split operands -------------
#define AP 20
#define BP 72

template <bool BIAS, bool RES, bool GEGLU>
__global__ __launch_bounds__(256) void tgemm_kernel(
    const uint32_t* __restrict__ Ahg, const uint32_t* __restrict__ Alg,
    const uint32_t* Bh0, const uint32_t* Bl0,
    const uint32_t* Bh1, const uint32_t* Bl1,
    const uint32_t* Bh2, const uint32_t* Bl2,
    const float* __restrict__ bias, const float* __restrict__ res,
    float* C0, float* C1, float* C2,
    uint32_t* __restrict__ Gh, uint32_t* __restrict__ Gl,
    int M, int N, int K2)
{
    const uint32_t* __restrict__ Bhg = (blockIdx.z == 0) ? Bh0 : (blockIdx.z == 1 ? Bh1 : Bh2);
    const uint32_t* __restrict__ Blg = (blockIdx.z == 0) ? Bl0 : (blockIdx.z == 1 ? Bl1 : Bl2);
    float* __restrict__ C            = (blockIdx.z == 0) ? C0  : (blockIdx.z == 1 ? C1  : C2);

    __shared__ uint32_t Ah[2][64][AP];
    __shared__ uint32_t Al[2][64][AP];
    __shared__ uint32_t Bh[2][16][BP];
    __shared__ uint32_t Bl[2][16][BP];

    int t = threadIdx.x;
    int w = t >> 5, lane = t & 31;
    int gid = lane >> 2, tig = lane & 3;
    int wm = (w >> 1) * 16, wn = (w & 1) * 32;
    int bm = blockIdx.y * 64, bn = blockIdx.x * 64;

    int a_row = t >> 2;
    int a_jj = (t & 3) * 4;
    int b_j = t >> 4;
    int b_c = (t & 15) * 4;
    int gm = bm + a_row;

    float acc[4][4];
    #pragma unroll
    for (int nt = 0; nt < 4; nt++)
        #pragma unroll
        for (int i = 0; i < 4; i++) acc[nt][i] = 0.f;

    uint4 aRh, aRl, bRh, bRl;
    const uint4 zz = make_uint4(0u, 0u, 0u, 0u);

    aRh = (gm < M) ? *(const uint4*)(Ahg + (size_t)gm * K2 + a_jj) : zz;
    aRl = (gm < M) ? *(const uint4*)(Alg + (size_t)gm * K2 + a_jj) : zz;
    bRh = *(const uint4*)(Bhg + (size_t)b_j * N + bn + b_c);
    bRl = *(const uint4*)(Blg + (size_t)b_j * N + bn + b_c);
    *(uint4*)&Ah[0][a_row][a_jj] = aRh;
    *(uint4*)&Al[0][a_row][a_jj] = aRl;
    *(uint4*)&Bh[0][b_j][b_c] = bRh;
    *(uint4*)&Bl[0][b_j][b_c] = bRl;
    __syncthreads();

    int nchunks = K2 >> 4;
    for (int it = 0; it < nchunks; it++) {
        int cur = it & 1;
        if (it + 1 < nchunks) {
            int k2_0 = (it + 1) << 4;
            aRh = (gm < M) ? *(const uint4*)(Ahg + (size_t)gm * K2 + k2_0 + a_jj) : zz;
            aRl = (gm < M) ? *(const uint4*)(Alg + (size_t)gm * K2 + k2_0 + a_jj) : zz;
            bRh = *(const uint4*)(Bhg + (size_t)(k2_0 + b_j) * N + bn + b_c);
            bRl = *(const uint4*)(Blg + (size_t)(k2_0 + b_j) * N + bn + b_c);
        }
        #pragma unroll
        for (int ks = 0; ks < 2; ks++) {
            int jb = ks * 8;
            uint32_t ah[4], al_[4];
            {
                int r = wm + gid;
                ah[0]  = Ah[cur][r][jb + tig];         al_[0] = Al[cur][r][jb + tig];
                ah[1]  = Ah[cur][r + 8][jb + tig];     al_[1] = Al[cur][r + 8][jb + tig];
                ah[2]  = Ah[cur][r][jb + tig + 4];     al_[2] = Al[cur][r][jb + tig + 4];
                ah[3]  = Ah[cur][r + 8][jb + tig + 4]; al_[3] = Al[cur][r + 8][jb + tig + 4];
            }
            uint32_t bh_[4][2], bl_[4][2];
            #pragma unroll
            for (int nt = 0; nt < 4; nt++) {
                int col = wn + nt * 8 + gid;
                bh_[nt][0] = Bh[cur][jb + tig][col];     bl_[nt][0] = Bl[cur][jb + tig][col];
                bh_[nt][1] = Bh[cur][jb + tig + 4][col]; bl_[nt][1] = Bl[cur][jb + tig + 4][col];
            }
            #pragma unroll
            for (int nt = 0; nt < 4; nt++) {
                mma_bf16(acc[nt], al_, bh_[nt]);
                mma_bf16(acc[nt], ah, bl_[nt]);
                mma_bf16(acc[nt], ah, bh_[nt]);
            }
        }
        if (it + 1 < nchunks) {
            int nxt = cur ^ 1;
            *(uint4*)&Ah[nxt][a_row][a_jj] = aRh;
            *(uint4*)&Al[nxt][a_row][a_jj] = aRl;
            *(uint4*)&Bh[nxt][b_j][b_c] = bRh;
            *(uint4*)&Bl[nxt][b_j][b_c] = bRl;
        }
        __syncthreads();
    }

    int r0 = bm + wm + gid;
    int r1 = r0 + 8;
    if (GEGLU) {
        #pragma unroll
        for (int nt = 0; nt < 4; nt++) {
            int col = bn + wn + nt * 8 + 2 * tig;
            float2 bv = *(const float2*)&bias[col];
            float a_r0 = acc[nt][0] + bv.x, g_r0 = acc[nt][1] + bv.y;
            float a_r1 = acc[nt][2] + bv.x, g_r1 = acc[nt][3] + bv.y;
            float gg0 = a_r0 * (0.5f * g_r0 * (1.f + erff(g_r0 * 0.70710678118654752f)));
            float gg1 = a_r1 * (0.5f * g_r1 * (1.f + erff(g_r1 * 0.70710678118654752f)));
            float p0 = __shfl_xor_sync(~0u, gg0, 1);
            float p1 = __shfl_xor_sync(~0u, gg1, 1);
            if ((tig & 1) == 0) {
                int wword = ((bn + wn + nt * 8) >> 2) + (tig >> 1);
                uint32_t h, l;
                if (r0 < M) {
                    split_pack(gg0, p0, h, l);
                    Gh[(size_t)r0 * K2FF + wword] = h;
                    Gl[(size_t)r0 * K2FF + wword] = l;
                }
                if (r1 < M) {
                    split_pack(gg1, p1, h, l);
                    Gh[(size_t)r1 * K2FF + wword] = h;
                    Gl[(size_t)r1 * K2FF + wword] = l;
                }
            }
        }
    } else {
        #pragma unroll
        for (int nt = 0; nt < 4; nt++) {
            int col = bn + wn + nt * 8 + 2 * tig;
            float2 bv = make_float2(0.f, 0.f);
            if (BIAS) bv = *(const float2*)&bias[col];
            float2 lo = make_float2(acc[nt][0] + bv.x, acc[nt][1] + bv.y);
            float2 hi = make_float2(acc[nt][2] + bv.x, acc[nt][3] + bv.y);
            if (r0 < M) {
                if (RES) {
                    float2 rv = *(const float2*)(res + (size_t)r0 * N + col);
                    lo.x += rv.x; lo.y += rv.y;
                }
                *(float2*)(C + (size_t)r0 * N + col) = lo;
            }
            if (r1 < M) {
                if (RES) {
                    float2 rv = *(const float2*)(res + (size_t)r1 * N + col);
                    hi.x += rv.x; hi.y += rv.y;
                }
                *(float2*)(C + (size_t)r1 * N + col) = hi;
            }
        }
    }
}

// ---------------- self-attention: tf32 mma flash, 8 warps, 128-key tiles --------
// Grid (32, 8); 256 threads; each warp owns ONE m16 tile. 128-key smem tiles,
// two 64-key compute passes per tile -> half the barrier count of r15.
// Dynamic smem: Ks(128x44) + Vs(128x44) + Ps(8x16x72) = 81920 B.
#define ATTN_SMEM (128 * 44 * 4 * 2 + 8 * 16 * 72 * 4)

__global__ __launch_bounds__(256) void self_attn_mma_kernel(
    const float* __restrict__ q, const float* __restrict__ k,
    const float* __restrict__ v, uint32_t* __restrict__ Oh,
    uint32_t* __restrict__ Ol)
{
    extern __shared__ float sm[];
    float* Ks = sm;                       // [128][44]
    float* Vs = sm + 128 * 44;            // [128][44]
    float* Ps = sm + 2 * 128 * 44;        // [8][16][72]

    int tid = threadIdx.x;
    int w = tid >> 5, lane = tid & 31;
    int gid = lane >> 2, tig = lane & 3;
    int head = blockIdx.y;
    int qbase = blockIdx.x * 128 + w * 16;
    float* Pw = Ps + w * (16 * 72);

    uint32_t qa[5][4];
    {
        const float* q0 = q + (size_t)(qbase + gid) * DIM + head * DHEAD;
        const float* q1 = q0 + 8 * DIM;
        #pragma unroll
        for (int ks = 0; ks < 5; ks++) {
            qa[ks][0] = __float_as_uint(q0[ks * 8 + tig] * (SCALE * LOG2E));
            qa[ks][1] = __float_as_uint(q1[ks * 8 + tig] * (SCALE * LOG2E));
            qa[ks][2] = __float_as_uint(q0[ks * 8 + tig + 4] * (SCALE * LOG2E));
            qa[ks][3] = __float_as_uint(q1[ks * 8 + tig + 4] * (SCALE * LOG2E));
        }
    }

    float o[5][4];
    #pragma unroll
    for (int n = 0; n < 5; n++)
        #pragma unroll
        for (int i = 0; i < 4; i++) o[n][i] = 0.f;
    float m0 = -1e30f, m1 = -1e30f, l0 = 0.f, l1 = 0.f;

    for (int kt = 0; kt < N_TOK; kt += 128) {
        __syncthreads();
        #pragma unroll
        for (int it = 0; it < 5; it++) {
            int idx = tid + it * 256;
            int row = idx / 10, c = idx % 10;
            size_t goff = (size_t)(kt + row) * DIM + head * DHEAD + c * 4;
            *(float4*)&Ks[row * 44 + c * 4] = *(const float4*)(k + goff);
            *(float4*)&Vs[row * 44 + c * 4] = *(const float4*)(v + goff);
        }
        __syncthreads();

        #pragma unroll
        for (int half = 0; half < 2; half++) {
            int kb = half * 64;
            float c[8][4];
            #pragma unroll
            for (int j = 0; j < 8; j++) {
                c[j][0] = 0.f; c[j][1] = 0.f; c[j][2] = 0.f; c[j][3] = 0.f;
                #pragma unroll
                for (int ks = 0; ks < 5; ks++) {
                    uint32_t b[2];
                    b[0] = __float_as_uint(Ks[(kb + j * 8 + gid) * 44 + ks * 8 + tig]);
                    b[1] = __float_as_uint(Ks[(kb + j * 8 + gid) * 44 + ks * 8 + tig + 4]);
                    mma_tf32(c[j], qa[ks], b);
                }
            }
            float mx0 = -1e30f, mx1 = -1e30f;
            #pragma unroll
            for (int j = 0; j < 8; j++) {
                mx0 = fmaxf(mx0, fmaxf(c[j][0], c[j][1]));
                mx1 = fmaxf(mx1, fmaxf(c[j][2], c[j][3]));
            }
            mx0 = fmaxf(mx0, __shfl_xor_sync(~0u, mx0, 1));
            mx0 = fmaxf(mx0, __shfl_xor_sync(~0u, mx0, 2));
            mx1 = fmaxf(mx1, __shfl_xor_sync(~0u, mx1, 1));
            mx1 = fmaxf(mx1, __shfl_xor_sync(~0u, mx1, 2));
            float mn0 = fmaxf(m0, mx0);
            float mn1 = fmaxf(m1, mx1);
            float cor0 = exp2f(m0 - mn0);
            float cor1 = exp2f(m1 - mn1);
            m0 = mn0; m1 = mn1;
            float sum0 = 0.f, sum1 = 0.f;
            #pragma unroll
            for (int j = 0; j < 8; j++) {
                c[j][0] = exp2f(c[j][0] - mn0);
                c[j][1] = exp2f(c[j][1] - mn0);
                c[j][2] = exp2f(c[j][2] - mn1);
                c[j][3] = exp2f(c[j][3] - mn1);
                sum0 += c[j][0] + c[j][1];
                sum1 += c[j][2] + c[j][3];
            }
            sum0 += __shfl_xor_sync(~0u, sum0, 1);
            sum0 += __shfl_xor_sync(~0u, sum0, 2);
            sum1 += __shfl_xor_sync(~0u, sum1, 1);
            sum1 += __shfl_xor_sync(~0u, sum1, 2);
            l0 = l0 * cor0 + sum0;
            l1 = l1 * cor1 + sum1;
            #pragma unroll
            for (int n = 0; n < 5; n++) {
                o[n][0] *= cor0; o[n][1] *= cor0;
                o[n][2] *= cor1; o[n][3] *= cor1;
            }
            __syncwarp();
            #pragma unroll
            for (int j = 0; j < 8; j++) {
                *(float2*)&Pw[gid * 72 + j * 8 + 2 * tig]       = make_float2(c[j][0], c[j][1]);
                *(float2*)&Pw[(gid + 8) * 72 + j * 8 + 2 * tig] = make_float2(c[j][2], c[j][3]);
            }
            __syncwarp();
            #pragma unroll
            for (int kk = 0; kk < 8; kk++) {
                uint32_t pa[4];
                pa[0] = __float_as_uint(Pw[gid * 72 + kk * 8 + tig]);
                pa[1] = __float_as_uint(Pw[(gid + 8) * 72 + kk * 8 + tig]);
                pa[2] = __float_as_uint(Pw[gid * 72 + kk * 8 + tig + 4]);
                pa[3] = __float_as_uint(Pw[(gid + 8) * 72 + kk * 8 + tig + 4]);
                #pragma unroll
                for (int n = 0; n < 5; n++) {
                    uint32_t vb[2];
                    vb[0] = __float_as_uint(Vs[(kb + kk * 8 + tig) * 44 + n * 8 + gid]);
                    vb[1] = __float_as_uint(Vs[(kb + kk * 8 + tig + 4) * 44 + n * 8 + gid]);
                    mma_tf32(o[n], pa, vb);
                }
            }
            __syncwarp();
        }
    }

    int hoff = head * (DHEAD / 2);
    {
        float inv0 = 1.f / l0;
        float inv1 = 1.f / l1;
        int r0 = qbase + gid;
        int r1 = r0 + 8;
        #pragma unroll
        for (int n = 0; n < 5; n++) {
            uint32_t h, l;
            split_pack(o[n][0] * inv0, o[n][1] * inv0, h, l);
            Oh[(size_t)r0 * K2DIM + hoff + n * 4 + tig] = h;
            Ol[(size_t)r0 * K2DIM + hoff + n * 4 + tig] = l;
            split_pack(o[n][2] * inv1, o[n][3] * inv1, h, l);
            Oh[(size_t)r1 * K2DIM + hoff + n * 4 + tig] = h;
            Ol[(size_t)r1 * K2DIM + hoff + n * 4 + tig] = l;
        }
    }
}

// ---------------- fused cross-attention: scores + FCA + softmax + AV ------------
__global__ __launch_bounds__(128) void cross_fused_kernel(
    const float* __restrict__ q, const float* __restrict__ kc,
    const float* __restrict__ vc, const float* __restrict__ fam,
    const int* __restrict__ use_fca_p,
    uint32_t* __restrict__ Oh, uint32_t* __restrict__ Ol)
{
    __shared__ float KV[M_CTX * DHEAD];
    __shared__ float fam_s[M_CTX * M_CTX];
    __shared__ float srow[32][81];

    int t = threadIdx.x;
    int qloc = t >> 2, tig = t & 3;
    int head = blockIdx.y;
    int qi = blockIdx.x * 32 + qloc;
    int use_fca = *use_fca_p;

    for (int i = t; i < M_CTX * DHEAD; i += 128) {
        int row = i / DHEAD, c = i - row * DHEAD;
        KV[i] = kc[(size_t)row * DIM + head * DHEAD + c];
    }
    for (int i = t; i < M_CTX * M_CTX; i += 128)
        fam_s[i] = fam[i];
    __syncthreads();

    float qr[DHEAD];
    {
        const float4* qp = (const float4*)(q + (size_t)qi * DIM + head * DHEAD);
        #pragma unroll
        for (int i = 0; i < 10; i++) {
            float4 v4 = qp[i];
            qr[4 * i + 0] = v4.x * SCALE; qr[4 * i + 1] = v4.y * SCALE;
            qr[4 * i + 2] = v4.z * SCALE; qr[4 * i + 3] = v4.w * SCALE;
        }
    }

    #pragma unroll 4
    for (int j = tig; j < M_CTX; j += 4) {
        const float* kr = &KV[j * DHEAD];
        float s0 = 0.f, s1 = 0.f;
        #pragma unroll
        for (int i = 0; i < DHEAD; i += 2) {
            s0 += qr[i] * kr[i];
            s1 += qr[i + 1] * kr[i + 1];
        }
        srow[qloc][j] = s0 + s1;
    }
    __syncwarp();

    if (use_fca != 0) {
        float f[20];
        float fmax_local = 0.f;
        #pragma unroll 2
        for (int idx = 0; idx < 20; idx++) {
            int d = tig + 4 * idx;
            f[idx] = -1.f;
            if (d < M_CTX) {
                float a0 = 0.f, a1 = 0.f;
                const float* fr = &fam_s[d * M_CTX];
                for (int kk = 0; kk < M_CTX - 1; kk += 2) {
                    a0 += srow[qloc][kk] * fr[kk];
                    a1 += srow[qloc][kk + 1] * fr[kk + 1];
                }
                float a = a0 + a1 + srow[qloc][M_CTX - 1] * fr[M_CTX - 1];
                f[idx] = fminf(fabsf(a), 1.f);
                fmax_local = fmaxf(fmax_local, f[idx]);
            }
        }
        fmax_local = fmaxf(fmax_local, __shfl_xor_sync(~0u, fmax_local, 1));
        fmax_local = fmaxf(fmax_local, __shfl_xor_sync(~0u, fmax_local, 2));
        float denom = fmax_local + 1e-6f;
        __syncwarp();
        #pragma unroll
        for (int idx = 0; idx < 20; idx++) {
            int d = tig + 4 * idx;
            if (d < M_CTX) {
                float keep = (f[idx] / denom > 0.6f) ? 0.f : -50.f;
                srow[qloc][d] += keep;
            }
        }
        __syncwarp();
    }

    float p[20];
    float mloc = -1e30f;
    #pragma unroll
    for (int idx = 0; idx < 20; idx++) {
        int j = tig + 4 * idx;
        p[idx] = (j < M_CTX) ? srow[qloc][j] : -1e30f;
        mloc = fmaxf(mloc, p[idx]);
    }
    mloc = fmaxf(mloc, __shfl_xor_sync(~0u, mloc, 1));
    mloc = fmaxf(mloc, __shfl_xor_sync(~0u, mloc, 2));
    float ssum = 0.f;
    #pragma unroll
    for (int idx = 0; idx < 20; idx++) {
        int j = tig + 4 * idx;
        if (j < M_CTX) { p[idx] = __expf(p[idx] - mloc); ssum += p[idx]; }
        else p[idx] = 0.f;
    }
    ssum += __shfl_xor_sync(~0u, ssum, 1);
    ssum += __shfl_xor_sync(~0u, ssum, 2);
    float inv = 1.f / ssum;
    #pragma unroll
    for (int idx = 0; idx < 20; idx++) p[idx] *= inv;

    __syncthreads();
    for (int i = t; i < M_CTX * DHEAD; i += 128) {
        int row = i / DHEAD, c = i - row * DHEAD;
        KV[i] = vc[(size_t)row * DIM + head * DHEAD + c];
    }
    __syncthreads();

    float o[DHEAD];
    #pragma unroll
    for (int i = 0; i < DHEAD; i++) o[i] = 0.f;
    #pragma unroll 2
    for (int idx = 0; idx < 20; idx++) {
        int j = tig + 4 * idx;
        if (j < M_CTX) {
            float pj = p[idx];
            const float* vr = &KV[j * DHEAD];
            #pragma unroll
            for (int i = 0; i < DHEAD; i++) o[i] += pj * vr[i];
        }
    }
    #pragma unroll
    for (int i = 0; i < DHEAD; i++) {
        o[i] += __shfl_xor_sync(~0u, o[i], 1);
        o[i] += __shfl_xor_sync(~0u, o[i], 2);
    }

    int hoff = head * (DHEAD / 2);
    #pragma unroll
    for (int s = 0; s < 5; s++) {
        int wword = tig + 4 * s;
        uint32_t h, l;
        split_pack(o[2 * wword], o[2 * wword + 1], h, l);
        Oh[(size_t)qi * K2DIM + hoff + wword] = h;
        Ol[(size_t)qi * K2DIM + hoff + wword] = l;
    }
}

// ---------------- launch ---------------------------------------------------------
extern "C" void kernel_launch(void* const* d_in, const int* in_sizes, int n_in,
                              void* d_out, int out_size)
{
    const float* x    = (const float*)d_in[0];
    const float* ctx  = (const float*)d_in[1];
    const float* fam  = (const float*)d_in[2];
    const float* g1   = (const float*)d_in[3];
    const float* b1   = (const float*)d_in[4];
    const float* g2   = (const float*)d_in[5];
    const float* b2   = (const float*)d_in[6];
    const float* g3   = (const float*)d_in[7];
    const float* b3   = (const float*)d_in[8];
    const float* Wq1  = (const float*)d_in[9];
    const float* Wk1  = (const float*)d_in[10];
    const float* Wv1  = (const float*)d_in[11];
    const float* Wo1  = (const float*)d_in[12];
    const float* bo1  = (const float*)d_in[13];
    const float* Wq2  = (const float*)d_in[14];
    const float* Wk2  = (const float*)d_in[15];
    const float* Wv2  = (const float*)d_in[16];
    const float* Wo2  = (const float*)d_in[17];
    const float* bo2  = (const float*)d_in[18];
    const float* Wff1 = (const float*)d_in[19];
    const float* bff1 = (const float*)d_in[20];
    const float* Wff2 = (const float*)d_in[21];
    const float* bff2 = (const float*)d_in[22];
    const int*   ufca = (const int*)d_in[23];
    float* out = (float*)d_out;

    float *q, *k, *v, *kc, *vc, *bff1p;
    uint32_t *hh, *hl, *oh, *ol, *ggh, *ggl, *cth, *ctl, *wh, *wl;
    cudaGetSymbolAddress((void**)&q,  g_q);
    cudaGetSymbolAddress((void**)&k,  g_k);
    cudaGetSymbolAddress((void**)&v,  g_v);
    cudaGetSymbolAddress((void**)&kc, g_kc);
    cudaGetSymbolAddress((void**)&vc, g_vc);
    cudaGetSymbolAddress((void**)&bff1p, g_bff1p);
    cudaGetSymbolAddress((void**)&hh, g_hh);
    cudaGetSymbolAddress((void**)&hl, g_hl);
    cudaGetSymbolAddress((void**)&oh, g_oh);
    cudaGetSymbolAddress((void**)&ol, g_ol);
    cudaGetSymbolAddress((void**)&ggh, g_ggh);
    cudaGetSymbolAddress((void**)&ggl, g_ggl);
    cudaGetSymbolAddress((void**)&cth, g_ctxh);
    cudaGetSymbolAddress((void**)&ctl, g_ctxl);
    cudaGetSymbolAddress((void**)&wh, g_wh);
    cudaGetSymbolAddress((void**)&wl, g_wl);

    static int smem_set = 0;
    if (!smem_set) {
        cudaFuncSetAttribute(self_attn_mma_kernel,
                             cudaFuncAttributeMaxDynamicSharedMemorySize, ATTN_SMEM);
        smem_set = 1;
    }

    WTable tab;
    const float* srcs[10] = { Wq1, Wk1, Wv1, Wo1, Wq2, Wo2, Wk2, Wv2, Wff1, Wff2 };
    const int offs[10] = { WQ1_OFF, WK1_OFF, WV1_OFF, WO1_OFF, WQ2_OFF, WO2_OFF,
                           WK2_OFF, WV2_OFF, WFF1_OFF, WFF2_OFF };
    const int ns[10]   = { DIM, DIM, DIM, DIM, DIM, DIM, DIM, DIM, 2 * FF_INNER, DIM };
    const int wrds[10] = { 51200, 51200, 51200, 51200, 51200, 51200,
                           122880, 122880, 409600, 204800 };
    for (int i = 0; i < 10; i++) {
        tab.j[i].src = srcs[i];
        tab.j[i].dh = wh + offs[i];
        tab.j[i].dl = wl + offs[i];
        tab.j[i].N = ns[i];
        tab.j[i].words = wrds[i];
        tab.j[i].permute = (i == 8) ? 1 : 0;
    }
    split_w_kernel<<<dim3(1600, 1, 10), 256>>>(tab);
    split_a_kernel<<<(M_CTX * K2CTX + 255) / 256, 256>>>(ctx, cth, ctl, K2CTX, M_CTX * K2CTX);
    perm_bias_kernel<<<(2 * FF_INNER + 255) / 256, 256>>>(bff1, bff1p);

    dim3 g_mm(DIM / 64, N_TOK / 64, 1);
    dim3 g_qkv(DIM / 64, N_TOK / 64, 3);
    dim3 g_ctx2(DIM / 64, 2, 2);
    dim3 g_ff1(2 * FF_INNER / 64, N_TOK / 64, 1);

    // --- block 1: self-attention ---
    ln_kernel<<<N_TOK / 8, 256>>>(x, g1, b1, hh, hl);
    tgemm_kernel<false, false, false><<<g_qkv, 256>>>(hh, hl,
        wh + WQ1_OFF, wl + WQ1_OFF, wh + WK1_OFF, wl + WK1_OFF, wh + WV1_OFF, wl + WV1_OFF,
        nullptr, nullptr, q, k, v, nullptr, nullptr, N_TOK, DIM, K2DIM);
    self_attn_mma_kernel<<<dim3(N_TOK / 128, HEADS), 256, ATTN_SMEM>>>(q, k, v, oh, ol);
    tgemm_kernel<true, true, false><<<g_mm, 256>>>(oh, ol,
        wh + WO1_OFF, wl + WO1_OFF, wh + WO1_OFF, wl + WO1_OFF, wh + WO1_OFF, wl + WO1_OFF,
        bo1, x, out, out, out, nullptr, nullptr, N_TOK, DIM, K2DIM);

    // --- block 2: cross-attention with FCA (fused) ---
    ln_kernel<<<N_TOK / 8, 256>>>(out, g2, b2, hh, hl);
    tgemm_kernel<false, false, false><<<g_mm, 256>>>(hh, hl,
        wh + WQ2_OFF, wl + WQ2_OFF, wh + WQ2_OFF, wl + WQ2_OFF, wh + WQ2_OFF, wl + WQ2_OFF,
        nullptr, nullptr, q, q, q, nullptr, nullptr, N_TOK, DIM, K2DIM);
    tgemm_kernel<false, false, false><<<g_ctx2, 256>>>(cth, ctl,
        wh + WK2_OFF, wl + WK2_OFF, wh + WV2_OFF, wl + WV2_OFF, wh + WV2_OFF, wl + WV2_OFF,
        nullptr, nullptr, kc, vc, vc, nullptr, nullptr, M_CTX, DIM, K2CTX);
    cross_fused_kernel<<<dim3(N_TOK / 32, HEADS), 128>>>(q, kc, vc, fam, ufca, oh, ol);
    tgemm_kernel<true, true, false><<<g_mm, 256>>>(oh, ol,
        wh + WO2_OFF, wl + WO2_OFF, wh + WO2_OFF, wl + WO2_OFF, wh + WO2_OFF, wl + WO2_OFF,
        bo2, out, out, out, out, nullptr, nullptr, N_TOK, DIM, K2DIM);

    // --- block 3: GEGLU feed-forward (fused into ff1 GEMM epilogue) ---
    ln_kernel<<<N_TOK / 8, 256>>>(out, g3, b3, hh, hl);
    tgemm_kernel<true, false, true><<<g_ff1, 256>>>(hh, hl,
        wh + WFF1_OFF, wl + WFF1_OFF, wh + WFF1_OFF, wl + WFF1_OFF, wh + WFF1_OFF, wl + WFF1_OFF,
        bff1p, nullptr, nullptr, nullptr, nullptr, ggh, ggl, N_TOK, 2 * FF_INNER, K2DIM);
    tgemm_kernel<true, true, false><<<g_mm, 256>>>(ggh, ggl,
        wh + WFF2_OFF, wl + WFF2_OFF, wh + WFF2_OFF, wl + WFF2_OFF, wh + WFF2_OFF, wl + WFF2_OFF,
        bff2, out, out, out, out, nullptr, nullptr, N_TOK, DIM, K2FF);
}

// round 17
// speedup vs baseline: 1.0517x; 1.0517x over previous
#include <cuda_runtime.h>
#include <math.h>
#include <stdint.h>

#define N_TOK 4096
#define DIM 320
#define HEADS 8
#define DHEAD 40
#define CTX_DIM 768
#define M_CTX 77
#define FF_INNER 1280
#define SCALE 0.15811388300841898f
#define LOG2E 1.4426950408889634f
#define K2DIM 160
#define K2CTX 384
#define K2FF 640

typedef unsigned long long ull;

// ---------------- tf32 m16n8k8 mma (attention) ---------------------------------
__device__ __forceinline__ void mma_tf32(float* d, const uint32_t* a, const uint32_t* b) {
    asm volatile("mma.sync.aligned.m16n8k8.row.col.f32.tf32.tf32.f32 "
        "{%0,%1,%2,%3}, {%4,%5,%6,%7}, {%8,%9}, {%0,%1,%2,%3};"
        : "+f"(d[0]), "+f"(d[1]), "+f"(d[2]), "+f"(d[3])
        : "r"(a[0]), "r"(a[1]), "r"(a[2]), "r"(a[3]), "r"(b[0]), "r"(b[1]));
}

// ---------------- bf16 m16n8k16 mma (GEMMs) -------------------------------------
__device__ __forceinline__ void mma_bf16(float* d, const uint32_t* a, const uint32_t* b) {
    asm volatile("mma.sync.aligned.m16n8k16.row.col.f32.bf16.bf16.f32 "
        "{%0,%1,%2,%3}, {%4,%5,%6,%7}, {%8,%9}, {%0,%1,%2,%3};"
        : "+f"(d[0]), "+f"(d[1]), "+f"(d[2]), "+f"(d[3])
        : "r"(a[0]), "r"(a[1]), "r"(a[2]), "r"(a[3]), "r"(b[0]), "r"(b[1]));
}

// split a pair of fp32 (x0=even k, x1=odd k) into packed bf16x2 hi + residual lo.
__device__ __forceinline__ void split_pack(float x0, float x1, uint32_t& h, uint32_t& l) {
    uint32_t hp;
    asm("cvt.rn.satfinite.bf16x2.f32 %0, %1, %2;" : "=r"(hp) : "f"(x1), "f"(x0));
    float f0 = __uint_as_float(hp << 16);
    float f1 = __uint_as_float(hp & 0xffff0000u);
    float r0 = x0 - f0;
    float r1 = x1 - f1;
    asm("cvt.rn.satfinite.bf16x2.f32 %0, %1, %2;" : "=r"(l) : "f"(r1), "f"(r0));
    h = hp;
}

// ---------------- scratch (device globals; no allocation allowed) ------------
__device__ float g_q[N_TOK * DIM];
__device__ float g_k[N_TOK * DIM];
__device__ float g_v[N_TOK * DIM];
__device__ float g_kc[M_CTX * DIM];
__device__ float g_vc[M_CTX * DIM];
__device__ float g_bff1p[2 * FF_INNER];
// split (packed bf16x2 hi/lo) activations
__device__ uint32_t g_hh[N_TOK * K2DIM];
__device__ uint32_t g_hl[N_TOK * K2DIM];
__device__ uint32_t g_oh[N_TOK * K2DIM];
__device__ uint32_t g_ol[N_TOK * K2DIM];
__device__ uint32_t g_ggh[N_TOK * K2FF];
__device__ uint32_t g_ggl[N_TOK * K2FF];
__device__ uint32_t g_ctxh[M_CTX * K2CTX];
__device__ uint32_t g_ctxl[M_CTX * K2CTX];
// split weights
#define WQ1_OFF 0
#define WK1_OFF 51200
#define WV1_OFF 102400
#define WO1_OFF 153600
#define WQ2_OFF 204800
#define WO2_OFF 256000
#define WK2_OFF 307200
#define WV2_OFF 430080
#define WFF1_OFF 552960
#define WFF2_OFF 962560
#define W_TOTAL 1167360
__device__ uint32_t g_wh[W_TOTAL];
__device__ uint32_t g_wl[W_TOTAL];

// ---------------- weight split prep ([K/2][N] packed pairs, optional col perm) --
struct WJob { const float* src; uint32_t* dh; uint32_t* dl; int N; int words; int permute; };
struct WTable { WJob j[10]; };

__global__ __launch_bounds__(256) void split_w_kernel(WTable tab) {
    WJob jb = tab.j[blockIdx.z];
    int half = jb.N >> 1;
    for (int w = blockIdx.x * 256 + threadIdx.x; w < jb.words; w += gridDim.x * 256) {
        int jj = w / jb.N, n = w - jj * jb.N;
        float x0 = jb.src[(size_t)(2 * jj) * jb.N + n];
        float x1 = jb.src[(size_t)(2 * jj + 1) * jb.N + n];
        uint32_t h, l; split_pack(x0, x1, h, l);
        int n2 = jb.permute ? ((n < half) ? 2 * n : 2 * (n - half) + 1) : n;
        jb.dh[(size_t)jj * jb.N + n2] = h;
        jb.dl[(size_t)jj * jb.N + n2] = l;
    }
}

// ---------------- bias permute for fused GEGLU -----------------------------------
__global__ __launch_bounds__(256) void perm_bias_kernel(const float* __restrict__ src,
                                                        float* __restrict__ dst) {
    int n = blockIdx.x * 256 + threadIdx.x;
    if (n >= 2 * FF_INNER) return;
    int n2 = (n < FF_INNER) ? 2 * n : 2 * (n - FF_INNER) + 1;
    dst[n2] = src[n];
}

// ---------------- A-operand split prep ([M][K/2] packed pairs) ------------------
__global__ __launch_bounds__(256) void split_a_kernel(const float* __restrict__ src,
                                                      uint32_t* __restrict__ dh,
                                                      uint32_t* __restrict__ dl,
                                                      int K2, int words) {
    int w = blockIdx.x * 256 + threadIdx.x;
    if (w >= words) return;
    int row = w / K2, p = w - row * K2;
    float x0 = src[(size_t)row * 2 * K2 + 2 * p];
    float x1 = src[(size_t)row * 2 * K2 + 2 * p + 1];
    uint32_t h, l; split_pack(x0, x1, h, l);
    dh[w] = h; dl[w] = l;
}

// ---------------- LayerNorm (warp per row, writes split bf16 pairs) -------------
__global__ __launch_bounds__(256) void ln_kernel(const float* __restrict__ x,
                                                 const float* __restrict__ g,
                                                 const float* __restrict__ b,
                                                 uint32_t* __restrict__ Hh,
                                                 uint32_t* __restrict__ Hl) {
    int w = threadIdx.x >> 5, lane = threadIdx.x & 31;
    int row = blockIdx.x * 8 + w;
    const float* xr = x + (size_t)row * DIM;
    float s = 0.f, s2 = 0.f;
    #pragma unroll
    for (int i = 0; i < 10; i++) {
        float v = xr[lane + 32 * i];
        s += v; s2 += v * v;
    }
    #pragma unroll
    for (int off = 16; off; off >>= 1) {
        s  += __shfl_xor_sync(~0u, s, off);
        s2 += __shfl_xor_sync(~0u, s2, off);
    }
    float mu = s * (1.f / DIM);
    float var = s2 * (1.f / DIM) - mu * mu;
    float rstd = rsqrtf(var + 1e-5f);
    #pragma unroll
    for (int sdx = 0; sdx < 5; sdx++) {
        int p = lane + 32 * sdx;
        float2 xv = *(const float2*)(xr + 2 * p);
        float2 gv = *(const float2*)(g + 2 * p);
        float2 bv = *(const float2*)(b + 2 * p);
        float x0 = (xv.x - mu) * rstd * gv.x + bv.x;
        float x1 = (xv.y - mu) * rstd * gv.y + bv.y;
        uint32_t h, l; split_pack(x0, x1, h, l);
        Hh[(size_t)row * K2DIM + p] = h;
        Hl[(size_t)row * K2DIM + p] = l;
    }
}

// ---------------- bf16x3 tensor-core GEMM 64x64, pre-split operands -------------
#define AP 20
#define BP 72

template <bool BIAS, bool RES, bool GEGLU>
__global__ __launch_bounds__(256) void tgemm_kernel(
    const uint32_t* __restrict__ Ahg, const uint32_t* __restrict__ Alg,
    const uint32_t* Bh0, const uint32_t* Bl0,
    const uint32_t* Bh1, const uint32_t* Bl1,
    const uint32_t* Bh2, const uint32_t* Bl2,
    const float* __restrict__ bias, const float* __restrict__ res,
    float* C0, float* C1, float* C2,
    uint32_t* __restrict__ Gh, uint32_t* __restrict__ Gl,
    int M, int N, int K2)
{
    const uint32_t* __restrict__ Bhg = (blockIdx.z == 0) ? Bh0 : (blockIdx.z == 1 ? Bh1 : Bh2);
    const uint32_t* __restrict__ Blg = (blockIdx.z == 0) ? Bl0 : (blockIdx.z == 1 ? Bl1 : Bl2);
    float* __restrict__ C            = (blockIdx.z == 0) ? C0  : (blockIdx.z == 1 ? C1  : C2);

    __shared__ uint32_t Ah[2][64][AP];
    __shared__ uint32_t Al[2][64][AP];
    __shared__ uint32_t Bh[2][16][BP];
    __shared__ uint32_t Bl[2][16][BP];

    int t = threadIdx.x;
    int w = t >> 5, lane = t & 31;
    int gid = lane >> 2, tig = lane & 3;
    int wm = (w >> 1) * 16, wn = (w & 1) * 32;
    int bm = blockIdx.y * 64, bn = blockIdx.x * 64;

    int a_row = t >> 2;
    int a_jj = (t & 3) * 4;
    int b_j = t >> 4;
    int b_c = (t & 15) * 4;
    int gm = bm + a_row;

    float acc[4][4];
    #pragma unroll
    for (int nt = 0; nt < 4; nt++)
        #pragma unroll
        for (int i = 0; i < 4; i++) acc[nt][i] = 0.f;

    uint4 aRh, aRl, bRh, bRl;
    const uint4 zz = make_uint4(0u, 0u, 0u, 0u);

    aRh = (gm < M) ? *(const uint4*)(Ahg + (size_t)gm * K2 + a_jj) : zz;
    aRl = (gm < M) ? *(const uint4*)(Alg + (size_t)gm * K2 + a_jj) : zz;
    bRh = *(const uint4*)(Bhg + (size_t)b_j * N + bn + b_c);
    bRl = *(const uint4*)(Blg + (size_t)b_j * N + bn + b_c);
    *(uint4*)&Ah[0][a_row][a_jj] = aRh;
    *(uint4*)&Al[0][a_row][a_jj] = aRl;
    *(uint4*)&Bh[0][b_j][b_c] = bRh;
    *(uint4*)&Bl[0][b_j][b_c] = bRl;
    __syncthreads();

    int nchunks = K2 >> 4;
    for (int it = 0; it < nchunks; it++) {
        int cur = it & 1;
        if (it + 1 < nchunks) {
            int k2_0 = (it + 1) << 4;
            aRh = (gm < M) ? *(const uint4*)(Ahg + (size_t)gm * K2 + k2_0 + a_jj) : zz;
            aRl = (gm < M) ? *(const uint4*)(Alg + (size_t)gm * K2 + k2_0 + a_jj) : zz;
            bRh = *(const uint4*)(Bhg + (size_t)(k2_0 + b_j) * N + bn + b_c);
            bRl = *(const uint4*)(Blg + (size_t)(k2_0 + b_j) * N + bn + b_c);
        }
        #pragma unroll
        for (int ks = 0; ks < 2; ks++) {
            int jb = ks * 8;
            uint32_t ah[4], al_[4];
            {
                int r = wm + gid;
                ah[0]  = Ah[cur][r][jb + tig];         al_[0] = Al[cur][r][jb + tig];
                ah[1]  = Ah[cur][r + 8][jb + tig];     al_[1] = Al[cur][r + 8][jb + tig];
                ah[2]  = Ah[cur][r][jb + tig + 4];     al_[2] = Al[cur][r][jb + tig + 4];
                ah[3]  = Ah[cur][r + 8][jb + tig + 4]; al_[3] = Al[cur][r + 8][jb + tig + 4];
            }
            uint32_t bh_[4][2], bl_[4][2];
            #pragma unroll
            for (int nt = 0; nt < 4; nt++) {
                int col = wn + nt * 8 + gid;
                bh_[nt][0] = Bh[cur][jb + tig][col];     bl_[nt][0] = Bl[cur][jb + tig][col];
                bh_[nt][1] = Bh[cur][jb + tig + 4][col]; bl_[nt][1] = Bl[cur][jb + tig + 4][col];
            }
            #pragma unroll
            for (int nt = 0; nt < 4; nt++) {
                mma_bf16(acc[nt], al_, bh_[nt]);
                mma_bf16(acc[nt], ah, bl_[nt]);
                mma_bf16(acc[nt], ah, bh_[nt]);
            }
        }
        if (it + 1 < nchunks) {
            int nxt = cur ^ 1;
            *(uint4*)&Ah[nxt][a_row][a_jj] = aRh;
            *(uint4*)&Al[nxt][a_row][a_jj] = aRl;
            *(uint4*)&Bh[nxt][b_j][b_c] = bRh;
            *(uint4*)&Bl[nxt][b_j][b_c] = bRl;
        }
        __syncthreads();
    }

    int r0 = bm + wm + gid;
    int r1 = r0 + 8;
    if (GEGLU) {
        #pragma unroll
        for (int nt = 0; nt < 4; nt++) {
            int col = bn + wn + nt * 8 + 2 * tig;
            float2 bv = *(const float2*)&bias[col];
            float a_r0 = acc[nt][0] + bv.x, g_r0 = acc[nt][1] + bv.y;
            float a_r1 = acc[nt][2] + bv.x, g_r1 = acc[nt][3] + bv.y;
            float gg0 = a_r0 * (0.5f * g_r0 * (1.f + erff(g_r0 * 0.70710678118654752f)));
            float gg1 = a_r1 * (0.5f * g_r1 * (1.f + erff(g_r1 * 0.70710678118654752f)));
            float p0 = __shfl_xor_sync(~0u, gg0, 1);
            float p1 = __shfl_xor_sync(~0u, gg1, 1);
            if ((tig & 1) == 0) {
                int wword = ((bn + wn + nt * 8) >> 2) + (tig >> 1);
                uint32_t h, l;
                if (r0 < M) {
                    split_pack(gg0, p0, h, l);
                    Gh[(size_t)r0 * K2FF + wword] = h;
                    Gl[(size_t)r0 * K2FF + wword] = l;
                }
                if (r1 < M) {
                    split_pack(gg1, p1, h, l);
                    Gh[(size_t)r1 * K2FF + wword] = h;
                    Gl[(size_t)r1 * K2FF + wword] = l;
                }
            }
        }
    } else {
        #pragma unroll
        for (int nt = 0; nt < 4; nt++) {
            int col = bn + wn + nt * 8 + 2 * tig;
            float2 bv = make_float2(0.f, 0.f);
            if (BIAS) bv = *(const float2*)&bias[col];
            float2 lo = make_float2(acc[nt][0] + bv.x, acc[nt][1] + bv.y);
            float2 hi = make_float2(acc[nt][2] + bv.x, acc[nt][3] + bv.y);
            if (r0 < M) {
                if (RES) {
                    float2 rv = *(const float2*)(res + (size_t)r0 * N + col);
                    lo.x += rv.x; lo.y += rv.y;
                }
                *(float2*)(C + (size_t)r0 * N + col) = lo;
            }
            if (r1 < M) {
                if (RES) {
                    float2 rv = *(const float2*)(res + (size_t)r1 * N + col);
                    hi.x += rv.x; hi.y += rv.y;
                }
                *(float2*)(C + (size_t)r1 * N + col) = hi;
            }
        }
    }
}

// ---------------- self-attention: tf32 mma flash, 8 warps / 128 q ---------------
// (round-15 configuration: 64-key tiles, each warp one m16 tile — best measured)
#define ATTN_SMEM (64 * 44 * 4 * 2 + 8 * 16 * 72 * 4)

__global__ __launch_bounds__(256) void self_attn_mma_kernel(
    const float* __restrict__ q, const float* __restrict__ k,
    const float* __restrict__ v, uint32_t* __restrict__ Oh,
    uint32_t* __restrict__ Ol)
{
    extern __shared__ float sm[];
    float* Ks = sm;                       // [64][44]
    float* Vs = sm + 64 * 44;             // [64][44]
    float* Ps = sm + 2 * 64 * 44;         // [8][16][72]

    int tid = threadIdx.x;
    int w = tid >> 5, lane = tid & 31;
    int gid = lane >> 2, tig = lane & 3;
    int head = blockIdx.y;
    int qbase = blockIdx.x * 128 + w * 16;
    float* Pw = Ps + w * (16 * 72);

    uint32_t qa[5][4];
    {
        const float* q0 = q + (size_t)(qbase + gid) * DIM + head * DHEAD;
        const float* q1 = q0 + 8 * DIM;
        #pragma unroll
        for (int ks = 0; ks < 5; ks++) {
            qa[ks][0] = __float_as_uint(q0[ks * 8 + tig] * (SCALE * LOG2E));
            qa[ks][1] = __float_as_uint(q1[ks * 8 + tig] * (SCALE * LOG2E));
            qa[ks][2] = __float_as_uint(q0[ks * 8 + tig + 4] * (SCALE * LOG2E));
            qa[ks][3] = __float_as_uint(q1[ks * 8 + tig + 4] * (SCALE * LOG2E));
        }
    }

    float o[5][4];
    #pragma unroll
    for (int n = 0; n < 5; n++)
        #pragma unroll
        for (int i = 0; i < 4; i++) o[n][i] = 0.f;
    float m0 = -1e30f, m1 = -1e30f, l0 = 0.f, l1 = 0.f;

    for (int kt = 0; kt < N_TOK; kt += 64) {
        __syncthreads();
        for (int idx = tid; idx < 640; idx += 256) {
            int row = idx / 10, c = idx % 10;
            size_t goff = (size_t)(kt + row) * DIM + head * DHEAD + c * 4;
            *(float4*)&Ks[row * 44 + c * 4] = *(const float4*)(k + goff);
            *(float4*)&Vs[row * 44 + c * 4] = *(const float4*)(v + goff);
        }
        __syncthreads();

        float c[8][4];
        #pragma unroll
        for (int j = 0; j < 8; j++) {
            c[j][0] = 0.f; c[j][1] = 0.f; c[j][2] = 0.f; c[j][3] = 0.f;
            #pragma unroll
            for (int ks = 0; ks < 5; ks++) {
                uint32_t b[2];
                b[0] = __float_as_uint(Ks[(j * 8 + gid) * 44 + ks * 8 + tig]);
                b[1] = __float_as_uint(Ks[(j * 8 + gid) * 44 + ks * 8 + tig + 4]);
                mma_tf32(c[j], qa[ks], b);
            }
        }
        float mx0 = -1e30f, mx1 = -1e30f;
        #pragma unroll
        for (int j = 0; j < 8; j++) {
            mx0 = fmaxf(mx0, fmaxf(c[j][0], c[j][1]));
            mx1 = fmaxf(mx1, fmaxf(c[j][2], c[j][3]));
        }
        mx0 = fmaxf(mx0, __shfl_xor_sync(~0u, mx0, 1));
        mx0 = fmaxf(mx0, __shfl_xor_sync(~0u, mx0, 2));
        mx1 = fmaxf(mx1, __shfl_xor_sync(~0u, mx1, 1));
        mx1 = fmaxf(mx1, __shfl_xor_sync(~0u, mx1, 2));
        float mn0 = fmaxf(m0, mx0);
        float mn1 = fmaxf(m1, mx1);
        float cor0 = exp2f(m0 - mn0);
        float cor1 = exp2f(m1 - mn1);
        m0 = mn0; m1 = mn1;
        float sum0 = 0.f, sum1 = 0.f;
        #pragma unroll
        for (int j = 0; j < 8; j++) {
            c[j][0] = exp2f(c[j][0] - mn0);
            c[j][1] = exp2f(c[j][1] - mn0);
            c[j][2] = exp2f(c[j][2] - mn1);
            c[j][3] = exp2f(c[j][3] - mn1);
            sum0 += c[j][0] + c[j][1];
            sum1 += c[j][2] + c[j][3];
        }
        sum0 += __shfl_xor_sync(~0u, sum0, 1);
        sum0 += __shfl_xor_sync(~0u, sum0, 2);
        sum1 += __shfl_xor_sync(~0u, sum1, 1);
        sum1 += __shfl_xor_sync(~0u, sum1, 2);
        l0 = l0 * cor0 + sum0;
        l1 = l1 * cor1 + sum1;
        #pragma unroll
        for (int n = 0; n < 5; n++) {
            o[n][0] *= cor0; o[n][1] *= cor0;
            o[n][2] *= cor1; o[n][3] *= cor1;
        }
        __syncwarp();
        #pragma unroll
        for (int j = 0; j < 8; j++) {
            *(float2*)&Pw[gid * 72 + j * 8 + 2 * tig]       = make_float2(c[j][0], c[j][1]);
            *(float2*)&Pw[(gid + 8) * 72 + j * 8 + 2 * tig] = make_float2(c[j][2], c[j][3]);
        }
        __syncwarp();
        #pragma unroll
        for (int kk = 0; kk < 8; kk++) {
            uint32_t pa[4];
            pa[0] = __float_as_uint(Pw[gid * 72 + kk * 8 + tig]);
            pa[1] = __float_as_uint(Pw[(gid + 8) * 72 + kk * 8 + tig]);
            pa[2] = __float_as_uint(Pw[gid * 72 + kk * 8 + tig + 4]);
            pa[3] = __float_as_uint(Pw[(gid + 8) * 72 + kk * 8 + tig + 4]);
            #pragma unroll
            for (int n = 0; n < 5; n++) {
                uint32_t vb[2];
                vb[0] = __float_as_uint(Vs[(kk * 8 + tig) * 44 + n * 8 + gid]);
                vb[1] = __float_as_uint(Vs[(kk * 8 + tig + 4) * 44 + n * 8 + gid]);
                mma_tf32(o[n], pa, vb);
            }
        }
        __syncwarp();
    }

    int hoff = head * (DHEAD / 2);
    {
        float inv0 = 1.f / l0;
        float inv1 = 1.f / l1;
        int r0 = qbase + gid;
        int r1 = r0 + 8;
        #pragma unroll
        for (int n = 0; n < 5; n++) {
            uint32_t h, l;
            split_pack(o[n][0] * inv0, o[n][1] * inv0, h, l);
            Oh[(size_t)r0 * K2DIM + hoff + n * 4 + tig] = h;
            Ol[(size_t)r0 * K2DIM + hoff + n * 4 + tig] = l;
            split_pack(o[n][2] * inv1, o[n][3] * inv1, h, l);
            Oh[(size_t)r1 * K2DIM + hoff + n * 4 + tig] = h;
            Ol[(size_t)r1 * K2DIM + hoff + n * 4 + tig] = l;
        }
    }
}

// ---------------- fused cross-attention: scores + FCA + softmax + AV ------------
__global__ __launch_bounds__(128) void cross_fused_kernel(
    const float* __restrict__ q, const float* __restrict__ kc,
    const float* __restrict__ vc, const float* __restrict__ fam,
    const int* __restrict__ use_fca_p,
    uint32_t* __restrict__ Oh, uint32_t* __restrict__ Ol)
{
    __shared__ float KV[M_CTX * DHEAD];
    __shared__ float fam_s[M_CTX * M_CTX];
    __shared__ float srow[32][81];

    int t = threadIdx.x;
    int qloc = t >> 2, tig = t & 3;
    int head = blockIdx.y;
    int qi = blockIdx.x * 32 + qloc;
    int use_fca = *use_fca_p;

    for (int i = t; i < M_CTX * DHEAD; i += 128) {
        int row = i / DHEAD, c = i - row * DHEAD;
        KV[i] = kc[(size_t)row * DIM + head * DHEAD + c];
    }
    for (int i = t; i < M_CTX * M_CTX; i += 128)
        fam_s[i] = fam[i];
    __syncthreads();

    float qr[DHEAD];
    {
        const float4* qp = (const float4*)(q + (size_t)qi * DIM + head * DHEAD);
        #pragma unroll
        for (int i = 0; i < 10; i++) {
            float4 v4 = qp[i];
            qr[4 * i + 0] = v4.x * SCALE; qr[4 * i + 1] = v4.y * SCALE;
            qr[4 * i + 2] = v4.z * SCALE; qr[4 * i + 3] = v4.w * SCALE;
        }
    }

    // scores for owned keys kept in registers AND mirrored to smem (FCA needs full row)
    float sreg[20];
    #pragma unroll 4
    for (int idx = 0; idx < 20; idx++) {
        int j = tig + 4 * idx;
        float sv = -1e30f;
        if (j < M_CTX) {
            const float* kr = &KV[j * DHEAD];
            float s0 = 0.f, s1 = 0.f;
            #pragma unroll
            for (int i = 0; i < DHEAD; i += 2) {
                s0 += qr[i] * kr[i];
                s1 += qr[i + 1] * kr[i + 1];
            }
            sv = s0 + s1;
            srow[qloc][j] = sv;
        }
        sreg[idx] = sv;
    }
    __syncwarp();

    if (use_fca != 0) {
        float f[20];
        float fmax_local = 0.f;
        #pragma unroll 2
        for (int idx = 0; idx < 20; idx++) {
            int d = tig + 4 * idx;
            f[idx] = -1.f;
            if (d < M_CTX) {
                float a0 = 0.f, a1 = 0.f;
                const float* fr = &fam_s[d * M_CTX];
                for (int kk = 0; kk < M_CTX - 1; kk += 2) {
                    a0 += srow[qloc][kk] * fr[kk];
                    a1 += srow[qloc][kk + 1] * fr[kk + 1];
                }
                float a = a0 + a1 + srow[qloc][M_CTX - 1] * fr[M_CTX - 1];
                f[idx] = fminf(fabsf(a), 1.f);
                fmax_local = fmaxf(fmax_local, f[idx]);
            }
        }
        fmax_local = fmaxf(fmax_local, __shfl_xor_sync(~0u, fmax_local, 1));
        fmax_local = fmaxf(fmax_local, __shfl_xor_sync(~0u, fmax_local, 2));
        float denom = fmax_local + 1e-6f;
        #pragma unroll
        for (int idx = 0; idx < 20; idx++) {
            int d = tig + 4 * idx;
            if (d < M_CTX) {
                float keep = (f[idx] / denom > 0.6f) ? 0.f : -50.f;
                sreg[idx] += keep;
            }
        }
    }

    // softmax over owned scores (registers)
    float mloc = -1e30f;
    #pragma unroll
    for (int idx = 0; idx < 20; idx++) mloc = fmaxf(mloc, sreg[idx]);
    mloc = fmaxf(mloc, __shfl_xor_sync(~0u, mloc, 1));
    mloc = fmaxf(mloc, __shfl_xor_sync(~0u, mloc, 2));
    float p[20];
    float ssum = 0.f;
    #pragma unroll
    for (int idx = 0; idx < 20; idx++) {
        int j = tig + 4 * idx;
        if (j < M_CTX) { p[idx] = __expf(sreg[idx] - mloc); ssum += p[idx]; }
        else p[idx] = 0.f;
    }
    ssum += __shfl_xor_sync(~0u, ssum, 1);
    ssum += __shfl_xor_sync(~0u, ssum, 2);
    float inv = 1.f / ssum;
    #pragma unroll
    for (int idx = 0; idx < 20; idx++) p[idx] *= inv;

    __syncthreads();
    for (int i = t; i < M_CTX * DHEAD; i += 128) {
        int row = i / DHEAD, c = i - row * DHEAD;
        KV[i] = vc[(size_t)row * DIM + head * DHEAD + c];
    }
    __syncthreads();

    float o[DHEAD];
    #pragma unroll
    for (int i = 0; i < DHEAD; i++) o[i] = 0.f;
    #pragma unroll 2
    for (int idx = 0; idx < 20; idx++) {
        int j = tig + 4 * idx;
        if (j < M_CTX) {
            float pj = p[idx];
            const float* vr = &KV[j * DHEAD];
            #pragma unroll
            for (int i = 0; i < DHEAD; i++) o[i] += pj * vr[i];
        }
    }
    #pragma unroll
    for (int i = 0; i < DHEAD; i++) {
        o[i] += __shfl_xor_sync(~0u, o[i], 1);
        o[i] += __shfl_xor_sync(~0u, o[i], 2);
    }

    int hoff = head * (DHEAD / 2);
    #pragma unroll
    for (int s = 0; s < 5; s++) {
        int wword = tig + 4 * s;
        uint32_t h, l;
        split_pack(o[2 * wword], o[2 * wword + 1], h, l);
        Oh[(size_t)qi * K2DIM + hoff + wword] = h;
        Ol[(size_t)qi * K2DIM + hoff + wword] = l;
    }
}

// ---------------- launch ---------------------------------------------------------
extern "C" void kernel_launch(void* const* d_in, const int* in_sizes, int n_in,
                              void* d_out, int out_size)
{
    const float* x    = (const float*)d_in[0];
    const float* ctx  = (const float*)d_in[1];
    const float* fam  = (const float*)d_in[2];
    const float* g1   = (const float*)d_in[3];
    const float* b1   = (const float*)d_in[4];
    const float* g2   = (const float*)d_in[5];
    const float* b2   = (const float*)d_in[6];
    const float* g3   = (const float*)d_in[7];
    const float* b3   = (const float*)d_in[8];
    const float* Wq1  = (const float*)d_in[9];
    const float* Wk1  = (const float*)d_in[10];
    const float* Wv1  = (const float*)d_in[11];
    const float* Wo1  = (const float*)d_in[12];
    const float* bo1  = (const float*)d_in[13];
    const float* Wq2  = (const float*)d_in[14];
    const float* Wk2  = (const float*)d_in[15];
    const float* Wv2  = (const float*)d_in[16];
    const float* Wo2  = (const float*)d_in[17];
    const float* bo2  = (const float*)d_in[18];
    const float* Wff1 = (const float*)d_in[19];
    const float* bff1 = (const float*)d_in[20];
    const float* Wff2 = (const float*)d_in[21];
    const float* bff2 = (const float*)d_in[22];
    const int*   ufca = (const int*)d_in[23];
    float* out = (float*)d_out;

    float *q, *k, *v, *kc, *vc, *bff1p;
    uint32_t *hh, *hl, *oh, *ol, *ggh, *ggl, *cth, *ctl, *wh, *wl;
    cudaGetSymbolAddress((void**)&q,  g_q);
    cudaGetSymbolAddress((void**)&k,  g_k);
    cudaGetSymbolAddress((void**)&v,  g_v);
    cudaGetSymbolAddress((void**)&kc, g_kc);
    cudaGetSymbolAddress((void**)&vc, g_vc);
    cudaGetSymbolAddress((void**)&bff1p, g_bff1p);
    cudaGetSymbolAddress((void**)&hh, g_hh);
    cudaGetSymbolAddress((void**)&hl, g_hl);
    cudaGetSymbolAddress((void**)&oh, g_oh);
    cudaGetSymbolAddress((void**)&ol, g_ol);
    cudaGetSymbolAddress((void**)&ggh, g_ggh);
    cudaGetSymbolAddress((void**)&ggl, g_ggl);
    cudaGetSymbolAddress((void**)&cth, g_ctxh);
    cudaGetSymbolAddress((void**)&ctl, g_ctxl);
    cudaGetSymbolAddress((void**)&wh, g_wh);
    cudaGetSymbolAddress((void**)&wl, g_wl);

    static int smem_set = 0;
    if (!smem_set) {
        cudaFuncSetAttribute(self_attn_mma_kernel,
                             cudaFuncAttributeMaxDynamicSharedMemorySize, ATTN_SMEM);
        smem_set = 1;
    }

    WTable tab;
    const float* srcs[10] = { Wq1, Wk1, Wv1, Wo1, Wq2, Wo2, Wk2, Wv2, Wff1, Wff2 };
    const int offs[10] = { WQ1_OFF, WK1_OFF, WV1_OFF, WO1_OFF, WQ2_OFF, WO2_OFF,
                           WK2_OFF, WV2_OFF, WFF1_OFF, WFF2_OFF };
    const int ns[10]   = { DIM, DIM, DIM, DIM, DIM, DIM, DIM, DIM, 2 * FF_INNER, DIM };
    const int wrds[10] = { 51200, 51200, 51200, 51200, 51200, 51200,
                           122880, 122880, 409600, 204800 };
    for (int i = 0; i < 10; i++) {
        tab.j[i].src = srcs[i];
        tab.j[i].dh = wh + offs[i];
        tab.j[i].dl = wl + offs[i];
        tab.j[i].N = ns[i];
        tab.j[i].words = wrds[i];
        tab.j[i].permute = (i == 8) ? 1 : 0;
    }
    split_w_kernel<<<dim3(1600, 1, 10), 256>>>(tab);
    split_a_kernel<<<(M_CTX * K2CTX + 255) / 256, 256>>>(ctx, cth, ctl, K2CTX, M_CTX * K2CTX);
    perm_bias_kernel<<<(2 * FF_INNER + 255) / 256, 256>>>(bff1, bff1p);

    dim3 g_mm(DIM / 64, N_TOK / 64, 1);
    dim3 g_qkv(DIM / 64, N_TOK / 64, 3);
    dim3 g_ctx2(DIM / 64, 2, 2);
    dim3 g_ff1(2 * FF_INNER / 64, N_TOK / 64, 1);

    // --- block 1: self-attention ---
    ln_kernel<<<N_TOK / 8, 256>>>(x, g1, b1, hh, hl);
    tgemm_kernel<false, false, false><<<g_qkv, 256>>>(hh, hl,
        wh + WQ1_OFF, wl + WQ1_OFF, wh + WK1_OFF, wl + WK1_OFF, wh + WV1_OFF, wl + WV1_OFF,
        nullptr, nullptr, q, k, v, nullptr, nullptr, N_TOK, DIM, K2DIM);
    self_attn_mma_kernel<<<dim3(N_TOK / 128, HEADS), 256, ATTN_SMEM>>>(q, k, v, oh, ol);
    tgemm_kernel<true, true, false><<<g_mm, 256>>>(oh, ol,
        wh + WO1_OFF, wl + WO1_OFF, wh + WO1_OFF, wl + WO1_OFF, wh + WO1_OFF, wl + WO1_OFF,
        bo1, x, out, out, out, nullptr, nullptr, N_TOK, DIM, K2DIM);

    // --- block 2: cross-attention with FCA (fused) ---
    ln_kernel<<<N_TOK / 8, 256>>>(out, g2, b2, hh, hl);
    tgemm_kernel<false, false, false><<<g_mm, 256>>>(hh, hl,
        wh + WQ2_OFF, wl + WQ2_OFF, wh + WQ2_OFF, wl + WQ2_OFF, wh + WQ2_OFF, wl + WQ2_OFF,
        nullptr, nullptr, q, q, q, nullptr, nullptr, N_TOK, DIM, K2DIM);
    tgemm_kernel<false, false, false><<<g_ctx2, 256>>>(cth, ctl,
        wh + WK2_OFF, wl + WK2_OFF, wh + WV2_OFF, wl + WV2_OFF, wh + WV2_OFF, wl + WV2_OFF,
        nullptr, nullptr, kc, vc, vc, nullptr, nullptr, M_CTX, DIM, K2CTX);
    cross_fused_kernel<<<dim3(N_TOK / 32, HEADS), 128>>>(q, kc, vc, fam, ufca, oh, ol);
    tgemm_kernel<true, true, false><<<g_mm, 256>>>(oh, ol,
        wh + WO2_OFF, wl + WO2_OFF, wh + WO2_OFF, wl + WO2_OFF, wh + WO2_OFF, wl + WO2_OFF,
        bo2, out, out, out, out, nullptr, nullptr, N_TOK, DIM, K2DIM);

    // --- block 3: GEGLU feed-forward (fused into ff1 GEMM epilogue) ---
    ln_kernel<<<N_TOK / 8, 256>>>(out, g3, b3, hh, hl);
    tgemm_kernel<true, false, true><<<g_ff1, 256>>>(hh, hl,
        wh + WFF1_OFF, wl + WFF1_OFF, wh + WFF1_OFF, wl + WFF1_OFF, wh + WFF1_OFF, wl + WFF1_OFF,
        bff1p, nullptr, nullptr, nullptr, nullptr, ggh, ggl, N_TOK, 2 * FF_INNER, K2DIM);
    tgemm_kernel<true, true, false><<<g_mm, 256>>>(ggh, ggl,
        wh + WFF2_OFF, wl + WFF2_OFF, wh + WFF2_OFF, wl + WFF2_OFF, wh + WFF2_OFF, wl + WFF2_OFF,
        bff2, out, out, out, out, nullptr, nullptr, N_TOK, DIM, K2FF);
}